// round 1
// baseline (speedup 1.0000x reference)
#include <cuda_runtime.h>

// Problem shape (fixed by the reference)
#define BB 64
#define SS 2048
#define HH 1024
#define NC 8            // S-chunks for flash partials
#define SC (SS/NC)      // 256 rows per chunk
#define NW 8            // warps per block (256 threads)
#define KS 8            // GEMM split-K slices
#define JT 16           // GEMM j-tiles (each 64 wide)
#define TK 32           // GEMM k-tile

// Scratch (static device globals: allocation-free)
__device__ float g_pacc[BB * NC * HH];   // per-chunk unnormalized acc (2 MB)
__device__ float g_pm[BB * NC];
__device__ float g_pl[BB * NC];
__device__ float g_attn[BB * HH];        // attn_applied (256 KB)
__device__ float g_gpart[KS * BB * HH];  // GEMM split-K partials (2 MB)

// ---------------------------------------------------------------------------
// Kernel 1: flash-style online-softmax attention partials.
// grid = (NC, BB), block = 256. Each warp owns an s-stripe of the chunk,
// keeps acc[32 floats]/lane in registers, merges across warps via smem.
// lstm_output is read exactly once (512 MB total traffic).
// ---------------------------------------------------------------------------
__global__ __launch_bounds__(256, 2)
void attn_partial_kernel(const float* __restrict__ lstm,
                         const float* __restrict__ hidden)
{
    const int b    = blockIdx.y;
    const int c    = blockIdx.x;
    const int tid  = threadIdx.x;
    const int w    = tid >> 5;
    const int lane = tid & 31;

    __shared__ float hs[HH];               // 4 KB
    __shared__ float waccs[NW][HH];        // 32 KB
    __shared__ float wms[NW], wls[NW];

    // Cache hidden[b] in smem
    const float4* hsrc = (const float4*)(hidden + (size_t)b * HH);
    for (int i = tid; i < HH / 4; i += 256) ((float4*)hs)[i] = hsrc[i];
    __syncthreads();

    const float4* hl = (const float4*)hs;

    float m = -1e30f, l = 0.f;
    float4 acc[8];
#pragma unroll
    for (int k = 0; k < 8; k++) acc[k] = make_float4(0.f, 0.f, 0.f, 0.f);

    const float* base = lstm + ((size_t)b * SS + (size_t)c * SC) * HH;

    for (int it = 0; it < SC / NW; it++) {
        const int s = it * NW + w;
        const float4* row = (const float4*)(base + (size_t)s * HH);

        float4 x[8];
#pragma unroll
        for (int k = 0; k < 8; k++) x[k] = row[k * 32 + lane];   // h = k*128 + lane*4

        // dot(lstm_row, hidden)
        float d = 0.f;
#pragma unroll
        for (int k = 0; k < 8; k++) {
            float4 h4 = hl[k * 32 + lane];
            d += x[k].x * h4.x + x[k].y * h4.y + x[k].z * h4.z + x[k].w * h4.w;
        }
#pragma unroll
        for (int off = 16; off; off >>= 1) d += __shfl_xor_sync(0xffffffffu, d, off);

        // online softmax update
        const float mn = fmaxf(m, d);
        const float sc = __expf(m - mn);
        const float wt = __expf(d - mn);
        l = l * sc + wt;
#pragma unroll
        for (int k = 0; k < 8; k++) {
            acc[k].x = acc[k].x * sc + wt * x[k].x;
            acc[k].y = acc[k].y * sc + wt * x[k].y;
            acc[k].z = acc[k].z * sc + wt * x[k].z;
            acc[k].w = acc[k].w * sc + wt * x[k].w;
        }
        m = mn;
    }

    if (lane == 0) { wms[w] = m; wls[w] = l; }
#pragma unroll
    for (int k = 0; k < 8; k++)
        *(float4*)&waccs[w][k * 128 + lane * 4] = acc[k];
    __syncthreads();

    // merge warps
    float gm = wms[0];
#pragma unroll
    for (int ww = 1; ww < NW; ww++) gm = fmaxf(gm, wms[ww]);
    float f[NW];
    float gl = 0.f;
#pragma unroll
    for (int ww = 0; ww < NW; ww++) {
        f[ww] = __expf(wms[ww] - gm);
        gl += wls[ww] * f[ww];
    }

    const int h0 = tid * 4;
    float4 sum = make_float4(0.f, 0.f, 0.f, 0.f);
#pragma unroll
    for (int ww = 0; ww < NW; ww++) {
        float4 v = *(float4*)&waccs[ww][h0];
        sum.x += f[ww] * v.x;  sum.y += f[ww] * v.y;
        sum.z += f[ww] * v.z;  sum.w += f[ww] * v.w;
    }
    const int pc = b * NC + c;
    *(float4*)&g_pacc[(size_t)pc * HH + h0] = sum;
    if (tid == 0) { g_pm[pc] = gm; g_pl[pc] = gl; }
}

// ---------------------------------------------------------------------------
// Kernel 2: merge chunk partials -> attn_applied[b,h]
// grid = BB, block = 256
// ---------------------------------------------------------------------------
__global__ void attn_combine_kernel()
{
    const int b   = blockIdx.x;
    const int tid = threadIdx.x;

    float pm[NC], pl[NC];
    float M = -1e30f;
#pragma unroll
    for (int c = 0; c < NC; c++) {
        pm[c] = g_pm[b * NC + c];
        pl[c] = g_pl[b * NC + c];
        M = fmaxf(M, pm[c]);
    }
    float f[NC];
    float L = 0.f;
#pragma unroll
    for (int c = 0; c < NC; c++) {
        f[c] = __expf(pm[c] - M);
        L += pl[c] * f[c];
    }
    const float inv = 1.f / L;

    const int h0 = tid * 4;
    float4 sum = make_float4(0.f, 0.f, 0.f, 0.f);
#pragma unroll
    for (int c = 0; c < NC; c++) {
        float4 v = *(const float4*)&g_pacc[(size_t)(b * NC + c) * HH + h0];
        sum.x += f[c] * v.x;  sum.y += f[c] * v.y;
        sum.z += f[c] * v.z;  sum.w += f[c] * v.w;
    }
    sum.x *= inv; sum.y *= inv; sum.z *= inv; sum.w *= inv;
    *(float4*)&g_attn[(size_t)b * HH + h0] = sum;
}

// ---------------------------------------------------------------------------
// Kernel 3: split-K GEMM partials: [hidden | attn] (64 x 2048) @ W^T (2048 x 1024)
// grid = (JT, KS), block = 256. Each block: 64b x 64j over a 256-wide k-slice.
// 4x4 register tiles per thread.
// ---------------------------------------------------------------------------
__global__ __launch_bounds__(256, 2)
void gemm_partial_kernel(const float* __restrict__ hidden,
                         const float* __restrict__ Wc)
{
    const int jt  = blockIdx.x;
    const int ks  = blockIdx.y;
    const int tid = threadIdx.x;

    __shared__ float As[64][TK + 1];
    __shared__ float Ws[64][TK + 1];

    const int tj = tid & 15;   // j group (0..15)
    const int tb = tid >> 4;   // b group (0..15)

    float acc[4][4];
#pragma unroll
    for (int i = 0; i < 4; i++)
#pragma unroll
        for (int j = 0; j < 4; j++) acc[i][j] = 0.f;

    const int k_base = ks * (2 * HH / KS);   // 256 per slice

    for (int k0 = 0; k0 < 2 * HH / KS; k0 += TK) {
        // A tile: combined[b][k] (k<H -> hidden, else attn). Slice is fully
        // one side of the boundary (k_base multiple of 256).
#pragma unroll
        for (int i = 0; i < 8; i++) {
            const int idx = i * 256 + tid;
            const int r   = idx >> 5;        // b
            const int col = idx & 31;        // k within tile
            const int k   = k_base + k0 + col;
            As[r][col] = (k < HH) ? hidden[(size_t)r * HH + k]
                                  : g_attn[(size_t)r * HH + (k - HH)];
        }
        // W tile: W[j][k]
#pragma unroll
        for (int i = 0; i < 8; i++) {
            const int idx = i * 256 + tid;
            const int r   = idx >> 5;        // j within tile
            const int col = idx & 31;
            Ws[r][col] = Wc[(size_t)(jt * 64 + r) * (2 * HH) + k_base + k0 + col];
        }
        __syncthreads();

#pragma unroll
        for (int kk = 0; kk < TK; kk++) {
            float a[4], wv[4];
#pragma unroll
            for (int i = 0; i < 4; i++) a[i]  = As[tb * 4 + i][kk];
#pragma unroll
            for (int i = 0; i < 4; i++) wv[i] = Ws[tj * 4 + i][kk];
#pragma unroll
            for (int i = 0; i < 4; i++)
#pragma unroll
                for (int j = 0; j < 4; j++) acc[i][j] += a[i] * wv[j];
        }
        __syncthreads();
    }

#pragma unroll
    for (int i = 0; i < 4; i++) {
        const int b = tb * 4 + i;
#pragma unroll
        for (int j = 0; j < 4; j++) {
            const int jg = jt * 64 + tj * 4 + j;
            g_gpart[((size_t)ks * BB + b) * HH + jg] = acc[i][j];
        }
    }
}

// ---------------------------------------------------------------------------
// Kernel 4: reduce split-K partials + bias -> out[b][j]
// grid = BB, block = 256
// ---------------------------------------------------------------------------
__global__ void gemm_reduce_kernel(const float* __restrict__ bias,
                                   float* __restrict__ out)
{
    const int b   = blockIdx.x;
    const int tid = threadIdx.x;
    const int j0  = tid * 4;

    float4 s = *(const float4*)&bias[j0];
#pragma unroll
    for (int k = 0; k < KS; k++) {
        float4 v = *(const float4*)&g_gpart[((size_t)k * BB + b) * HH + j0];
        s.x += v.x; s.y += v.y; s.z += v.z; s.w += v.w;
    }
    *(float4*)&out[(size_t)b * HH + j0] = s;
}

// ---------------------------------------------------------------------------
extern "C" void kernel_launch(void* const* d_in, const int* in_sizes, int n_in,
                              void* d_out, int out_size)
{
    const float* lstm   = (const float*)d_in[0];  // [B,S,H]
    const float* hidden = (const float*)d_in[1];  // [B,H]
    const float* Wc     = (const float*)d_in[2];  // [H,2H]
    const float* bias   = (const float*)d_in[3];  // [H]
    float* out          = (float*)d_out;          // [B,H]

    attn_partial_kernel<<<dim3(NC, BB), 256>>>(lstm, hidden);
    attn_combine_kernel<<<BB, 256>>>();
    gemm_partial_kernel<<<dim3(JT, KS), 256>>>(hidden, Wc);
    gemm_reduce_kernel<<<BB, 256>>>(bias, out);
}